// round 1
// baseline (speedup 1.0000x reference)
#include <cuda_runtime.h>
#include <cuda_bf16.h>
#include <math.h>

// Problem constants (fixed by the reference)
#define N_NODES  50000
#define N_EDGES  800000
#define D        128
#define N_GRAPHS 500
#define N_CLASS  16

// ---------------------------------------------------------------------------
// Scratch (device globals — no allocation allowed in kernel_launch)
// ---------------------------------------------------------------------------
__device__ float g_bufA[N_NODES * D];     // 25.6 MB
__device__ float g_bufB[N_NODES * D];     // 25.6 MB
__device__ int   g_rowptr[N_NODES + 1];   // CSR row pointers (by dst)
__device__ int   g_cursor[N_NODES];       // fill cursors
__device__ int   g_srcidx[N_EDGES];       // CSR column (src node per slot)
__device__ float g_pooled[N_GRAPHS * D];  // per-graph pooled features

// ---------------------------------------------------------------------------
// 0. zero rowptr + pooled
// ---------------------------------------------------------------------------
__global__ void zero_kernel() {
    int i = blockIdx.x * blockDim.x + threadIdx.x;
    if (i <= N_NODES) g_rowptr[i] = 0;
    if (i < N_GRAPHS * D) g_pooled[i] = 0.0f;
}

// ---------------------------------------------------------------------------
// 1. count in-degree per dst (offset by +1 for exclusive layout after scan)
// ---------------------------------------------------------------------------
__global__ void count_kernel(const int* __restrict__ edge_dst) {
    int e = blockIdx.x * blockDim.x + threadIdx.x;
    if (e < N_EDGES) atomicAdd(&g_rowptr[edge_dst[e] + 1], 1);
}

// ---------------------------------------------------------------------------
// 2. single-block inclusive scan over g_rowptr[0..N_NODES]; also seeds cursor
// ---------------------------------------------------------------------------
__global__ void scan_kernel() {
    __shared__ int sm[1024];
    const int tid = threadIdx.x;
    const int total = N_NODES + 1;
    int carry = 0;
    for (int base = 0; base < total; base += 1024) {
        int i = base + tid;
        int v = (i < total) ? g_rowptr[i] : 0;
        sm[tid] = v;
        __syncthreads();
        #pragma unroll
        for (int off = 1; off < 1024; off <<= 1) {
            int t = (tid >= off) ? sm[tid - off] : 0;
            __syncthreads();
            sm[tid] += t;
            __syncthreads();
        }
        int val = sm[tid] + carry;
        if (i < total) {
            g_rowptr[i] = val;
            if (i < N_NODES) g_cursor[i] = val;
        }
        carry += sm[1023];
        __syncthreads();
    }
}

// ---------------------------------------------------------------------------
// 3. fill CSR adjacency (src index per slot)
// ---------------------------------------------------------------------------
__global__ void fill_kernel(const int* __restrict__ edge_src,
                            const int* __restrict__ edge_dst) {
    int e = blockIdx.x * blockDim.x + threadIdx.x;
    if (e < N_EDGES) {
        int p = atomicAdd(&g_cursor[edge_dst[e]], 1);
        g_srcidx[p] = edge_src[e];
    }
}

// ---------------------------------------------------------------------------
// 4. propagate: out[i] = in[i] + sum_{(i<-j)} in[j]   (gather over CSR)
//    one warp per node, lane handles one float4 (32 lanes * 4 = 128 feats)
// ---------------------------------------------------------------------------
__global__ void prop_kernel(const float* __restrict__ in,
                            float* __restrict__ out) {
    int warp = (blockIdx.x * blockDim.x + threadIdx.x) >> 5;
    int lane = threadIdx.x & 31;
    if (warp >= N_NODES) return;

    const float4* __restrict__ in4 = (const float4*)in;
    float4 acc = in4[warp * 32 + lane];

    int beg = g_rowptr[warp];
    int end = g_rowptr[warp + 1];
    for (int e = beg; e < end; e++) {
        int s = g_srcidx[e];
        float4 v = in4[s * 32 + lane];
        acc.x += v.x; acc.y += v.y; acc.z += v.z; acc.w += v.w;
    }
    ((float4*)out)[warp * 32 + lane] = acc;
}

// ---------------------------------------------------------------------------
// 5. GEMM + bias (+optional relu): C[N,128] = A[N,128] @ W[128,128] + b
//    block = 128 threads, 32 rows per block; A tile in smem, W streamed.
// ---------------------------------------------------------------------------
template <bool RELU>
__global__ void gemm_kernel(const float* __restrict__ A,
                            const float* __restrict__ W,
                            const float* __restrict__ b,
                            float* __restrict__ C) {
    __shared__ float As[32][D];
    const int tid  = threadIdx.x;       // output column
    const int row0 = blockIdx.x * 32;

    #pragma unroll
    for (int r = 0; r < 32; r++) {
        int row = row0 + r;
        As[r][tid] = (row < N_NODES) ? A[row * D + tid] : 0.0f;
    }
    __syncthreads();

    float acc[32];
    #pragma unroll
    for (int r = 0; r < 32; r++) acc[r] = 0.0f;

    for (int k = 0; k < D; k += 4) {
        float w0 = W[(k + 0) * D + tid];
        float w1 = W[(k + 1) * D + tid];
        float w2 = W[(k + 2) * D + tid];
        float w3 = W[(k + 3) * D + tid];
        #pragma unroll
        for (int r = 0; r < 32; r++) {
            float4 a = *(const float4*)&As[r][k];
            acc[r] += a.x * w0 + a.y * w1 + a.z * w2 + a.w * w3;
        }
    }

    float bias = b[tid];
    #pragma unroll
    for (int r = 0; r < 32; r++) {
        int row = row0 + r;
        if (row < N_NODES) {
            float v = acc[r] + bias;
            if (RELU) v = fmaxf(v, 0.0f);
            C[row * D + tid] = v;
        }
    }
}

// ---------------------------------------------------------------------------
// 6. segmented pooling: pooled[idx[i]] += h[i]. idx is sorted, so each block
//    accumulates runs locally and emits only a few atomics at run boundaries.
// ---------------------------------------------------------------------------
#define POOL_ROWS 128
__global__ void pool_kernel(const float* __restrict__ h,
                            const int* __restrict__ idx) {
    const int tid = threadIdx.x;        // feature
    int r0 = blockIdx.x * POOL_ROWS;
    int r1 = min(r0 + POOL_ROWS, N_NODES);
    if (r0 >= N_NODES) return;

    int cur = idx[r0];
    float acc = 0.0f;
    for (int r = r0; r < r1; r++) {
        int g = idx[r];
        if (g != cur) {
            atomicAdd(&g_pooled[cur * D + tid], acc);
            acc = 0.0f;
            cur = g;
        }
        acc += h[r * D + tid];
    }
    atomicAdd(&g_pooled[cur * D + tid], acc);
}

// ---------------------------------------------------------------------------
// 7. graph head: zg = relu(pooled@W3+b3); out = log_softmax(zg@W4+b4)
//    one block (128 threads) per graph.
// ---------------------------------------------------------------------------
__global__ void head_kernel(const float* __restrict__ W3,
                            const float* __restrict__ b3,
                            const float* __restrict__ W4,
                            const float* __restrict__ b4,
                            float* __restrict__ out) {
    const int g   = blockIdx.x;
    const int tid = threadIdx.x;
    __shared__ float p[D];
    __shared__ float zg[D];
    __shared__ float o[N_CLASS];

    p[tid] = g_pooled[g * D + tid];
    __syncthreads();

    float acc = b3[tid];
    for (int k = 0; k < D; k++) acc += p[k] * W3[k * D + tid];
    zg[tid] = fmaxf(acc, 0.0f);
    __syncthreads();

    if (tid < N_CLASS) {
        float a = b4[tid];
        for (int k = 0; k < D; k++) a += zg[k] * W4[k * N_CLASS + tid];
        o[tid] = a;
    }
    __syncthreads();

    __shared__ float s_lse;
    if (tid == 0) {
        float m = o[0];
        for (int c = 1; c < N_CLASS; c++) m = fmaxf(m, o[c]);
        float s = 0.0f;
        for (int c = 0; c < N_CLASS; c++) s += expf(o[c] - m);
        s_lse = m + logf(s);
    }
    __syncthreads();
    if (tid < N_CLASS) out[g * N_CLASS + tid] = o[tid] - s_lse;
}

// ---------------------------------------------------------------------------
// Launch
// ---------------------------------------------------------------------------
extern "C" void kernel_launch(void* const* d_in, const int* in_sizes, int n_in,
                              void* d_out, int out_size) {
    const float* x        = (const float*)d_in[0];
    const int*   edge_src = (const int*)  d_in[1];
    const int*   edge_dst = (const int*)  d_in[2];
    const int*   idx      = (const int*)  d_in[3];
    const float* W1 = (const float*)d_in[4];
    const float* b1 = (const float*)d_in[5];
    const float* W2 = (const float*)d_in[6];
    const float* b2 = (const float*)d_in[7];
    const float* W3 = (const float*)d_in[8];
    const float* b3 = (const float*)d_in[9];
    const float* W4 = (const float*)d_in[10];
    const float* b4 = (const float*)d_in[11];
    float* out = (float*)d_out;

    float* bufA;  cudaGetSymbolAddress((void**)&bufA, g_bufA);
    float* bufB;  cudaGetSymbolAddress((void**)&bufB, g_bufB);

    // CSR build
    zero_kernel<<<(N_GRAPHS * D + 255) / 256, 256>>>();
    count_kernel<<<(N_EDGES + 255) / 256, 256>>>(edge_dst);
    scan_kernel<<<1, 1024>>>();
    fill_kernel<<<(N_EDGES + 255) / 256, 256>>>(edge_src, edge_dst);

    // Layer 1: t1 = prop(x); z1 = relu(t1 @ W1 + b1)
    prop_kernel<<<(N_NODES * 32 + 255) / 256, 256>>>(x, bufA);
    gemm_kernel<true><<<(N_NODES + 31) / 32, 128>>>(bufA, W1, b1, bufB);

    // Layer 2: t2 = prop(z1); h = t2 @ W2 + b2
    prop_kernel<<<(N_NODES * 32 + 255) / 256, 256>>>(bufB, bufA);
    gemm_kernel<false><<<(N_NODES + 31) / 32, 128>>>(bufA, W2, b2, bufB);

    // Pool + head
    pool_kernel<<<(N_NODES + POOL_ROWS - 1) / POOL_ROWS, D>>>(bufB, idx);
    head_kernel<<<N_GRAPHS, D>>>(W3, b3, W4, b4, out);
}

// round 2
// speedup vs baseline: 1.2476x; 1.2476x over previous
#include <cuda_runtime.h>
#include <cuda_bf16.h>
#include <math.h>

// Problem constants (fixed by the reference)
#define N_NODES  50000
#define N_EDGES  800000
#define D        128
#define N_GRAPHS 500
#define N_CLASS  16

#define SCAN_BLK 512
#define N_SCAN_BLOCKS ((N_NODES + 1 + SCAN_BLK - 1) / SCAN_BLK)  // 98

// ---------------------------------------------------------------------------
// Scratch (device globals — no allocation allowed in kernel_launch)
// ---------------------------------------------------------------------------
__device__ float  g_bufA[N_NODES * D];     // 25.6 MB
__device__ float  g_bufB[N_NODES * D];     // 25.6 MB
__device__ int    g_rowptr[N_NODES + 1];   // CSR row pointers (by dst)
__device__ int    g_cursor[N_NODES];       // fill cursors
__device__ int    g_srcidx[N_EDGES];       // CSR column (src node per slot)
__device__ float  g_pooled[N_GRAPHS * D];  // per-graph pooled features
__device__ int    g_bsum[N_SCAN_BLOCKS];   // scan block sums
__device__ int    g_boff[N_SCAN_BLOCKS];   // scan block offsets (exclusive)
__device__ float2 g_Wp1[64 * D];           // W1 pre-paired along K
__device__ float2 g_Wp2[64 * D];           // W2 pre-paired along K

// ---------------------------------------------------------------------------
// 0. zero rowptr + pooled
// ---------------------------------------------------------------------------
__global__ void zero_kernel() {
    int i = blockIdx.x * blockDim.x + threadIdx.x;
    if (i <= N_NODES) g_rowptr[i] = 0;
    if (i < N_GRAPHS * D) g_pooled[i] = 0.0f;
}

// ---------------------------------------------------------------------------
// 1. count in-degree per dst (offset by +1 for exclusive layout after scan)
// ---------------------------------------------------------------------------
__global__ void count_kernel(const int* __restrict__ edge_dst) {
    int e = blockIdx.x * blockDim.x + threadIdx.x;
    if (e < N_EDGES) atomicAdd(&g_rowptr[edge_dst[e] + 1], 1);
}

// ---------------------------------------------------------------------------
// 2a. per-block inclusive scan (in place) + block sums
// ---------------------------------------------------------------------------
__global__ void scanA_kernel() {
    __shared__ int sm[SCAN_BLK];
    const int tid = threadIdx.x;
    const int i = blockIdx.x * SCAN_BLK + tid;
    int v = (i <= N_NODES) ? g_rowptr[i] : 0;
    sm[tid] = v;
    __syncthreads();
    #pragma unroll
    for (int off = 1; off < SCAN_BLK; off <<= 1) {
        int t = (tid >= off) ? sm[tid - off] : 0;
        __syncthreads();
        sm[tid] += t;
        __syncthreads();
    }
    if (i <= N_NODES) g_rowptr[i] = sm[tid];
    if (tid == SCAN_BLK - 1) g_bsum[blockIdx.x] = sm[tid];
}

// ---------------------------------------------------------------------------
// 2b. scan the 98 block sums (single block, exclusive result into g_boff)
// ---------------------------------------------------------------------------
__global__ void scanB_kernel() {
    __shared__ int sm[128];
    const int tid = threadIdx.x;
    int v = (tid < N_SCAN_BLOCKS) ? g_bsum[tid] : 0;
    sm[tid] = v;
    __syncthreads();
    #pragma unroll
    for (int off = 1; off < 128; off <<= 1) {
        int t = (tid >= off) ? sm[tid - off] : 0;
        __syncthreads();
        sm[tid] += t;
        __syncthreads();
    }
    if (tid < N_SCAN_BLOCKS) g_boff[tid] = sm[tid] - v;  // exclusive
}

// ---------------------------------------------------------------------------
// 2c. add block offsets, seed cursors
// ---------------------------------------------------------------------------
__global__ void scanC_kernel() {
    int i = blockIdx.x * blockDim.x + threadIdx.x;
    if (i <= N_NODES) {
        int v = g_rowptr[i] + g_boff[i / SCAN_BLK];
        g_rowptr[i] = v;
        if (i < N_NODES) g_cursor[i] = v;
    }
}

// ---------------------------------------------------------------------------
// 3. fill CSR adjacency (src index per slot)
// ---------------------------------------------------------------------------
__global__ void fill_kernel(const int* __restrict__ edge_src,
                            const int* __restrict__ edge_dst) {
    int e = blockIdx.x * blockDim.x + threadIdx.x;
    if (e < N_EDGES) {
        int p = atomicAdd(&g_cursor[edge_dst[e]], 1);
        g_srcidx[p] = edge_src[e];
    }
}

// ---------------------------------------------------------------------------
// 3b. pre-pair weights along K for packed f32x2 GEMM:
//     Wp[kk][c] = { W[2kk][c], W[2kk+1][c] }
// ---------------------------------------------------------------------------
__global__ void wpair_kernel(const float* __restrict__ W1,
                             const float* __restrict__ W2) {
    int i = blockIdx.x * blockDim.x + threadIdx.x;
    if (i < 64 * D) {
        int kk = i >> 7;
        int c  = i & (D - 1);
        g_Wp1[i] = make_float2(W1[(2 * kk) * D + c], W1[(2 * kk + 1) * D + c]);
        g_Wp2[i] = make_float2(W2[(2 * kk) * D + c], W2[(2 * kk + 1) * D + c]);
    }
}

// ---------------------------------------------------------------------------
// 4. propagate: out[i] = in[i] + sum_{(i<-j)} in[j]   (gather over CSR)
//    one warp per node; 32 src indices batch-loaded coalesced then shfl'd;
//    4-way unrolled independent gathers for MLP.
// ---------------------------------------------------------------------------
__global__ void prop_kernel(const float* __restrict__ in,
                            float* __restrict__ out) {
    int warp = (blockIdx.x * blockDim.x + threadIdx.x) >> 5;
    int lane = threadIdx.x & 31;
    if (warp >= N_NODES) return;

    const float4* __restrict__ in4 = (const float4*)in;
    float4 acc = in4[warp * 32 + lane];

    int beg = g_rowptr[warp];
    int end = g_rowptr[warp + 1];
    for (int e = beg; e < end; e += 32) {
        int ii = e + lane;
        int s = (ii < end) ? g_srcidx[ii] : 0;
        int m = min(end - e, 32);
        int j = 0;
        for (; j + 4 <= m; j += 4) {
            int s0 = __shfl_sync(0xffffffffu, s, j + 0);
            int s1 = __shfl_sync(0xffffffffu, s, j + 1);
            int s2 = __shfl_sync(0xffffffffu, s, j + 2);
            int s3 = __shfl_sync(0xffffffffu, s, j + 3);
            float4 v0 = in4[s0 * 32 + lane];
            float4 v1 = in4[s1 * 32 + lane];
            float4 v2 = in4[s2 * 32 + lane];
            float4 v3 = in4[s3 * 32 + lane];
            acc.x += (v0.x + v1.x) + (v2.x + v3.x);
            acc.y += (v0.y + v1.y) + (v2.y + v3.y);
            acc.z += (v0.z + v1.z) + (v2.z + v3.z);
            acc.w += (v0.w + v1.w) + (v2.w + v3.w);
        }
        for (; j < m; j++) {
            int s0 = __shfl_sync(0xffffffffu, s, j);
            float4 v = in4[s0 * 32 + lane];
            acc.x += v.x; acc.y += v.y; acc.z += v.z; acc.w += v.w;
        }
    }
    ((float4*)out)[warp * 32 + lane] = acc;
}

// ---------------------------------------------------------------------------
// 5. packed-f32x2 GEMM + bias (+optional relu):
//    C[N,128] = A[N,128] @ W[128,128] + b
//    64 rows per block, 128 threads (thread = output column).
//    Accumulator f32x2 splits the K-sum into (even-k, odd-k) partials;
//    a-pair = contiguous LDS.64 broadcast, w-pair = pre-paired global (L1 hit).
// ---------------------------------------------------------------------------
__device__ __forceinline__ void fma2(unsigned long long& acc,
                                     unsigned long long a,
                                     unsigned long long w) {
    asm("fma.rn.f32x2 %0, %1, %2, %0;" : "+l"(acc) : "l"(a), "l"(w));
}

template <bool RELU>
__global__ __launch_bounds__(128)
void gemm2_kernel(const float* __restrict__ A,
                  const float2* __restrict__ Wp,
                  const float* __restrict__ b,
                  float* __restrict__ C) {
    __shared__ float As[64][D];
    const int tid  = threadIdx.x;         // output column
    const int row0 = blockIdx.x * 64;

    #pragma unroll 4
    for (int r = 0; r < 64; r++) {
        int row = row0 + r;
        As[r][tid] = (row < N_NODES) ? A[row * D + tid] : 0.0f;
    }
    __syncthreads();

    const unsigned long long* __restrict__ WpU =
        (const unsigned long long*)Wp;
    const float bias = b[tid];

    #pragma unroll
    for (int ch = 0; ch < 4; ch++) {
        unsigned long long acc[16];
        #pragma unroll
        for (int i = 0; i < 16; i++) acc[i] = 0ull;

        #pragma unroll 2
        for (int kk = 0; kk < 64; kk++) {
            unsigned long long wp = WpU[kk * D + tid];   // L1-resident
            #pragma unroll
            for (int i = 0; i < 16; i++) {
                unsigned long long a =
                    *(const unsigned long long*)&As[ch * 16 + i][2 * kk];
                fma2(acc[i], a, wp);
            }
        }

        #pragma unroll
        for (int i = 0; i < 16; i++) {
            int row = row0 + ch * 16 + i;
            if (row < N_NODES) {
                float lo = __uint_as_float((unsigned)(acc[i] & 0xffffffffull));
                float hi = __uint_as_float((unsigned)(acc[i] >> 32));
                float v = (lo + hi) + bias;
                if (RELU) v = fmaxf(v, 0.0f);
                C[row * D + tid] = v;
            }
        }
    }
}

// ---------------------------------------------------------------------------
// 6. segmented pooling: pooled[idx[i]] += h[i]. idx is sorted; run-local
//    accumulation, atomics only at run boundaries.
// ---------------------------------------------------------------------------
#define POOL_ROWS 128
__global__ void pool_kernel(const float* __restrict__ h,
                            const int* __restrict__ idx) {
    const int tid = threadIdx.x;        // feature
    int r0 = blockIdx.x * POOL_ROWS;
    int r1 = min(r0 + POOL_ROWS, N_NODES);
    if (r0 >= N_NODES) return;

    int cur = idx[r0];
    float acc = 0.0f;
    for (int r = r0; r < r1; r++) {
        int g = idx[r];
        if (g != cur) {
            atomicAdd(&g_pooled[cur * D + tid], acc);
            acc = 0.0f;
            cur = g;
        }
        acc += h[r * D + tid];
    }
    atomicAdd(&g_pooled[cur * D + tid], acc);
}

// ---------------------------------------------------------------------------
// 7. graph head: zg = relu(pooled@W3+b3); out = log_softmax(zg@W4+b4)
// ---------------------------------------------------------------------------
__global__ void head_kernel(const float* __restrict__ W3,
                            const float* __restrict__ b3,
                            const float* __restrict__ W4,
                            const float* __restrict__ b4,
                            float* __restrict__ out) {
    const int g   = blockIdx.x;
    const int tid = threadIdx.x;
    __shared__ float p[D];
    __shared__ float zg[D];
    __shared__ float o[N_CLASS];

    p[tid] = g_pooled[g * D + tid];
    __syncthreads();

    float acc = b3[tid];
    for (int k = 0; k < D; k++) acc += p[k] * W3[k * D + tid];
    zg[tid] = fmaxf(acc, 0.0f);
    __syncthreads();

    if (tid < N_CLASS) {
        float a = b4[tid];
        for (int k = 0; k < D; k++) a += zg[k] * W4[k * N_CLASS + tid];
        o[tid] = a;
    }
    __syncthreads();

    __shared__ float s_lse;
    if (tid == 0) {
        float m = o[0];
        for (int c = 1; c < N_CLASS; c++) m = fmaxf(m, o[c]);
        float s = 0.0f;
        for (int c = 0; c < N_CLASS; c++) s += expf(o[c] - m);
        s_lse = m + logf(s);
    }
    __syncthreads();
    if (tid < N_CLASS) out[g * N_CLASS + tid] = o[tid] - s_lse;
}

// ---------------------------------------------------------------------------
// Launch
// ---------------------------------------------------------------------------
extern "C" void kernel_launch(void* const* d_in, const int* in_sizes, int n_in,
                              void* d_out, int out_size) {
    const float* x        = (const float*)d_in[0];
    const int*   edge_src = (const int*)  d_in[1];
    const int*   edge_dst = (const int*)  d_in[2];
    const int*   idx      = (const int*)  d_in[3];
    const float* W1 = (const float*)d_in[4];
    const float* b1 = (const float*)d_in[5];
    const float* W2 = (const float*)d_in[6];
    const float* b2 = (const float*)d_in[7];
    const float* W3 = (const float*)d_in[8];
    const float* b3 = (const float*)d_in[9];
    const float* W4 = (const float*)d_in[10];
    const float* b4 = (const float*)d_in[11];
    float* out = (float*)d_out;

    float*  bufA; cudaGetSymbolAddress((void**)&bufA, g_bufA);
    float*  bufB; cudaGetSymbolAddress((void**)&bufB, g_bufB);
    float2* wp1;  cudaGetSymbolAddress((void**)&wp1, g_Wp1);
    float2* wp2;  cudaGetSymbolAddress((void**)&wp2, g_Wp2);

    // CSR build + weight pre-pairing
    zero_kernel<<<(N_GRAPHS * D + 255) / 256, 256>>>();
    wpair_kernel<<<(64 * D + 255) / 256, 256>>>(W1, W2);
    count_kernel<<<(N_EDGES + 255) / 256, 256>>>(edge_dst);
    scanA_kernel<<<N_SCAN_BLOCKS, SCAN_BLK>>>();
    scanB_kernel<<<1, 128>>>();
    scanC_kernel<<<(N_NODES + 256) / 256, 256>>>();
    fill_kernel<<<(N_EDGES + 255) / 256, 256>>>(edge_src, edge_dst);

    // Layer 1: t1 = prop(x); z1 = relu(t1 @ W1 + b1)
    prop_kernel<<<(N_NODES * 32 + 255) / 256, 256>>>(x, bufA);
    gemm2_kernel<true><<<(N_NODES + 63) / 64, 128>>>(bufA, wp1, b1, bufB);

    // Layer 2: t2 = prop(z1); h = t2 @ W2 + b2
    prop_kernel<<<(N_NODES * 32 + 255) / 256, 256>>>(bufB, bufA);
    gemm2_kernel<false><<<(N_NODES + 63) / 64, 128>>>(bufA, wp2, b2, bufB);

    // Pool + head
    pool_kernel<<<(N_NODES + POOL_ROWS - 1) / POOL_ROWS, D>>>(bufB, idx);
    head_kernel<<<N_GRAPHS, D>>>(W3, b3, W4, b4, out);
}